// round 15
// baseline (speedup 1.0000x reference)
#include <cuda_runtime.h>
#include <cuda_bf16.h>
#include <cstdint>

#define NN 50000
#define EE 800000
#define DD 128
#define LL 5
#define GG 1000

#define SCAN_B 512
#define NB ((NN + SCAN_B - 1) / SCAN_B)   // 98

// ---------------------------------------------------------------------------
// Device global scratch (no allocation allowed)
// ---------------------------------------------------------------------------
__device__ float g_z[NN * DD];
__device__ float g_h[2][NN * DD];
__device__ int g_deg[NN];      // zero on entry; boundary_kernel restores
__device__ int g_off[NN];
__device__ int g_cursor[NN];   // zero on entry; boundary_kernel restores
__device__ int g_adj[EE];
__device__ int g_scan[NB * SCAN_B];
__device__ int g_bsums[NB];
__device__ int g_gstart[GG];
__device__ int g_gend[GG];
// Pre-split weight images [mat(0=W1,1=W2)][layer][k*128+n]
__device__ __nv_bfloat16 g_wh[2][LL][DD * DD];
__device__ __nv_bfloat16 g_wl[2][LL][DD * DD];

// ---------------------------------------------------------------------------
// CSR build
// ---------------------------------------------------------------------------
__global__ void deg_count_kernel(const int* __restrict__ ei) {
    int e = blockIdx.x * blockDim.x + threadIdx.x;   // exact grid EE/256
    atomicAdd(&g_deg[ei[EE + e]], 1);
}
__global__ void scan_blocks_kernel() {
    __shared__ int s[SCAN_B];
    int tid = threadIdx.x;
    int i = blockIdx.x * SCAN_B + tid;
    int v = (i < NN) ? g_deg[i] : 0;
    s[tid] = v;
    __syncthreads();
#pragma unroll
    for (int o = 1; o < SCAN_B; o <<= 1) {
        int t = 0;
        if (tid >= o) t = s[tid - o];
        __syncthreads();
        s[tid] += t;
        __syncthreads();
    }
    g_scan[i] = s[tid];
    if (tid == SCAN_B - 1) g_bsums[blockIdx.x] = s[tid];
}
// fill_off with the top-level scan fused in (each block reduces bsums itself)
__global__ void fill_off_kernel() {
    __shared__ int warp_s[8];
    __shared__ int boff_s;
    const int tid = threadIdx.x;
    const int sb = blockIdx.x >> 1;            // scan-bucket of this block
    int v = (tid < NB && tid < sb) ? g_bsums[tid] : 0;
#pragma unroll
    for (int o = 16; o > 0; o >>= 1)
        v += __shfl_down_sync(0xffffffffu, v, o);
    if ((tid & 31) == 0) warp_s[tid >> 5] = v;
    __syncthreads();
    if (tid == 0) {
        int s = 0;
#pragma unroll
        for (int w = 0; w < 8; ++w) s += warp_s[w];
        boff_s = s;
    }
    __syncthreads();
    int i = blockIdx.x * 256 + tid;
    if (i < NN) g_off[i] = g_scan[i] - g_deg[i] + boff_s;
}
__global__ void fill_adj_kernel(const int* __restrict__ ei) {
    int e = blockIdx.x * blockDim.x + threadIdx.x;
    int dst = ei[EE + e];
    int pos = atomicAdd(&g_cursor[dst], 1);
    g_adj[g_off[dst] + pos] = ei[e];
}

// Graph boundary detection (batch is sorted) + deg/cursor cleanup for replays.
__global__ void boundary_kernel(const int* __restrict__ batch) {
    int i = blockIdx.x * blockDim.x + threadIdx.x;
    if (i < NN) {
        int b = batch[i];
        if (i == 0 || batch[i - 1] != b) g_gstart[b] = i;
        if (i == NN - 1 || batch[i + 1] != b) g_gend[b] = i + 1;
    }
}

// ---------------------------------------------------------------------------
// Weight pre-split + boundary-array init (fused)
// ---------------------------------------------------------------------------
__global__ void prep_w_kernel(const float* __restrict__ W1s,
                              const float* __restrict__ W2s) {
    int idx = blockIdx.x * 256 + threadIdx.x;   // 640*256 = 163840 exact
    int l = idx / 32768;
    int rem = idx & 32767;
    int mat = rem >> 14;
    int e = rem & 16383;
    const float* W = mat ? W2s : W1s;
    float w = W[(size_t)l * 16384 + e];
    __nv_bfloat16 hi = __float2bfloat16(w);
    float lo = w - __bfloat162float(hi);
    g_wh[mat][l][e] = hi;
    g_wl[mat][l][e] = __float2bfloat16(lo);
    if (idx < GG) { g_gstart[idx] = 0; g_gend[idx] = 0; }
}

// ---------------------------------------------------------------------------
// Gather: z = h + sum_{j in adj(node)} h[j]   (high occupancy, LTS roofline)
// ---------------------------------------------------------------------------
__global__ __launch_bounds__(256) void gather_kernel(const float* __restrict__ x,
                                                     int insel) {
    const float* cur = (insel < 0) ? x : g_h[insel];
    int t = blockIdx.x * 256 + threadIdx.x;
    int node = t >> 5;
    int lane = t & 31;
    int off = 0, deg = 0;
    if (lane == 0) { off = g_off[node]; deg = g_deg[node]; }
    off = __shfl_sync(0xffffffffu, off, 0);
    deg = __shfl_sync(0xffffffffu, deg, 0);
    float4 acc = reinterpret_cast<const float4*>(cur + (size_t)node * DD)[lane];
    for (int j0 = 0; j0 < deg; j0 += 32) {
        int myidx = 0;
        if (j0 + lane < deg) myidx = g_adj[off + j0 + lane];
        int cnt = min(32, deg - j0);
        int tt = 0;
        for (; tt + 4 <= cnt; tt += 4) {
            int s0 = __shfl_sync(0xffffffffu, myidx, tt);
            int s1 = __shfl_sync(0xffffffffu, myidx, tt + 1);
            int s2 = __shfl_sync(0xffffffffu, myidx, tt + 2);
            int s3 = __shfl_sync(0xffffffffu, myidx, tt + 3);
            float4 v0 = reinterpret_cast<const float4*>(cur + (size_t)s0 * DD)[lane];
            float4 v1 = reinterpret_cast<const float4*>(cur + (size_t)s1 * DD)[lane];
            float4 v2 = reinterpret_cast<const float4*>(cur + (size_t)s2 * DD)[lane];
            float4 v3 = reinterpret_cast<const float4*>(cur + (size_t)s3 * DD)[lane];
            acc.x += v0.x; acc.y += v0.y; acc.z += v0.z; acc.w += v0.w;
            acc.x += v1.x; acc.y += v1.y; acc.z += v1.z; acc.w += v1.w;
            acc.x += v2.x; acc.y += v2.y; acc.z += v2.z; acc.w += v2.w;
            acc.x += v3.x; acc.y += v3.y; acc.z += v3.z; acc.w += v3.w;
        }
        for (; tt < cnt; ++tt) {
            int s0 = __shfl_sync(0xffffffffu, myidx, tt);
            float4 v0 = reinterpret_cast<const float4*>(cur + (size_t)s0 * DD)[lane];
            acc.x += v0.x; acc.y += v0.y; acc.z += v0.z; acc.w += v0.w;
        }
    }
    reinterpret_cast<float4*>(g_z + (size_t)node * DD)[lane] = acc;
}

// ---------------------------------------------------------------------------
// Raw mma.sync bf16 3-split fused 2-layer MLP (non-persistent, 391 CTAs).
// 128 rows/CTA, 256 threads = 8 warps tiled 4(row) x 2(col).
// W2 smem copy deferred until after GEMM1 issue (overlaps mma drain).
// ---------------------------------------------------------------------------
#define LDA 136
#define A_HI_OFF 0
#define A_LO_OFF 34816
#define B_OFF(m, p) (69632 + (m) * 69632 + (p) * 34816)
#define BIAS_OFF 208896
#define MLP_SMEM (BIAS_OFF + 256 * 4)   // 209920 bytes

__device__ __forceinline__ uint32_t smem_u32(const void* p) {
    uint32_t a;
    asm("{ .reg .u64 t; cvta.to.shared.u64 t, %1; cvt.u32.u64 %0, t; }"
        : "=r"(a) : "l"(p));
    return a;
}
__device__ __forceinline__ void ldsm_x4(uint32_t* r, uint32_t addr) {
    asm volatile("ldmatrix.sync.aligned.m8n8.x4.shared.b16 {%0,%1,%2,%3}, [%4];"
                 : "=r"(r[0]), "=r"(r[1]), "=r"(r[2]), "=r"(r[3]) : "r"(addr));
}
__device__ __forceinline__ void ldsm_x4t(uint32_t* r, uint32_t addr) {
    asm volatile("ldmatrix.sync.aligned.m8n8.x4.trans.shared.b16 {%0,%1,%2,%3}, [%4];"
                 : "=r"(r[0]), "=r"(r[1]), "=r"(r[2]), "=r"(r[3]) : "r"(addr));
}
__device__ __forceinline__ void mma16816(float* c, const uint32_t* a,
                                         const uint32_t* b) {
    asm volatile("mma.sync.aligned.m16n8k16.row.col.f32.bf16.bf16.f32 "
                 "{%0,%1,%2,%3}, {%4,%5,%6,%7}, {%8,%9}, {%0,%1,%2,%3};"
                 : "+f"(c[0]), "+f"(c[1]), "+f"(c[2]), "+f"(c[3])
                 : "r"(a[0]), "r"(a[1]), "r"(a[2]), "r"(a[3]),
                   "r"(b[0]), "r"(b[1]));
}
__device__ __forceinline__ void copy_w_to_smem(char* dst,
                                               const __nv_bfloat16* src,
                                               int tid) {
#pragma unroll
    for (int it = 0; it < 8; ++it) {
        int idx = it * 256 + tid;       // 2048 uint4 total
        int k = idx >> 4;
        int q = idx & 15;
        *reinterpret_cast<uint4*>(dst + (size_t)k * (LDA * 2) + q * 16) =
            reinterpret_cast<const uint4*>(src + (size_t)k * DD)[q];
    }
}

__global__ __launch_bounds__(256) void mlp_mma_kernel(
    int l, int outsel,
    const float* __restrict__ b1s, const float* __restrict__ b2s) {
    extern __shared__ char sm[];
    float* bias = reinterpret_cast<float*>(sm + BIAS_OFF);

    const int tid = threadIdx.x;
    const int wid = tid >> 5;
    const int lane = tid & 31;
    const int wr = wid >> 1;          // 0..3 row tile
    const int wc = wid & 1;           // 0..1 col tile
    const int row0 = blockIdx.x * 128;

    const uint32_t ah_b = smem_u32(sm + A_HI_OFF);
    const uint32_t al_b = smem_u32(sm + A_LO_OFF);
    const uint32_t b1h = smem_u32(sm + B_OFF(0, 0));
    const uint32_t b1l = smem_u32(sm + B_OFF(0, 1));
    const uint32_t b2h = smem_u32(sm + B_OFF(1, 0));
    const uint32_t b2l = smem_u32(sm + B_OFF(1, 1));

    if (tid < 128) bias[tid] = b1s[(size_t)l * DD + tid];
    else bias[tid] = b2s[(size_t)l * DD + (tid - 128)];

    // W1 upfront (needed by GEMM1); W2 deferred to overlap GEMM1.
    copy_w_to_smem(sm + B_OFF(0, 0), g_wh[0][l], tid);
    copy_w_to_smem(sm + B_OFF(0, 1), g_wl[0][l], tid);

    // z rows -> split into Ah/Al
#pragma unroll
    for (int it = 0; it < 16; ++it) {
        int i = it * 256 + tid;
        int r = i >> 5, c4 = i & 31;
        int grow = row0 + r;
        float4 v = make_float4(0.f, 0.f, 0.f, 0.f);
        if (grow < NN)
            v = *reinterpret_cast<const float4*>(g_z + (size_t)grow * DD + c4 * 4);
        __nv_bfloat16 hx = __float2bfloat16(v.x), hy = __float2bfloat16(v.y);
        __nv_bfloat16 hz = __float2bfloat16(v.z), hw = __float2bfloat16(v.w);
        __nv_bfloat162 ph0(hx, hy), ph1(hz, hw);
        __nv_bfloat162 pl0(__float2bfloat16(v.x - __bfloat162float(hx)),
                           __float2bfloat16(v.y - __bfloat162float(hy)));
        __nv_bfloat162 pl1(__float2bfloat16(v.z - __bfloat162float(hz)),
                           __float2bfloat16(v.w - __bfloat162float(hw)));
        uint2 hi, lo;
        hi.x = *reinterpret_cast<uint32_t*>(&ph0);
        hi.y = *reinterpret_cast<uint32_t*>(&ph1);
        lo.x = *reinterpret_cast<uint32_t*>(&pl0);
        lo.y = *reinterpret_cast<uint32_t*>(&pl1);
        size_t boff = (size_t)r * (LDA * 2) + c4 * 8;
        *reinterpret_cast<uint2*>(sm + A_HI_OFF + boff) = hi;
        *reinterpret_cast<uint2*>(sm + A_LO_OFF + boff) = lo;
    }
    __syncthreads();

    const int a_row = lane & 15;
    const int a_koff = (lane >> 4) * 8;
    const int b_krow = (lane & 7) + ((lane >> 3) & 1) * 8;
    const int b_noff = (lane >> 4) * 8;
    const int eg = lane >> 2;
    const int et = 2 * (lane & 3);

    float cf[2][8][4];

    // ================= GEMM1 =================
#pragma unroll
    for (int i = 0; i < 2; ++i)
#pragma unroll
        for (int j = 0; j < 8; ++j)
#pragma unroll
            for (int q = 0; q < 4; ++q) cf[i][j][q] = 0.f;
    {
        const uint32_t Ab[3] = {ah_b, ah_b, al_b};
        const uint32_t Bb[3] = {b1h, b1l, b1h};
#pragma unroll
        for (int p = 0; p < 3; ++p)
#pragma unroll
            for (int k = 0; k < 8; ++k) {
                uint32_t a[2][4];
#pragma unroll
                for (int i = 0; i < 2; ++i)
                    ldsm_x4(a[i], Ab[p] +
                        ((wr * 32 + i * 16 + a_row) * LDA + k * 16 + a_koff) * 2);
                uint32_t b[8][2];
#pragma unroll
                for (int q = 0; q < 4; ++q) {
                    uint32_t r4[4];
                    ldsm_x4t(r4, Bb[p] +
                        ((k * 16 + b_krow) * LDA + wc * 64 + q * 16 + b_noff) * 2);
                    b[2 * q][0] = r4[0]; b[2 * q][1] = r4[1];
                    b[2 * q + 1][0] = r4[2]; b[2 * q + 1][1] = r4[3];
                }
#pragma unroll
                for (int i = 0; i < 2; ++i)
#pragma unroll
                    for (int j = 0; j < 8; ++j)
                        mma16816(cf[i][j], a[i], b[j]);
            }
    }
    // deferred W2 copy: LDGs overlap GEMM1 pipeline drain; visible to all
    // warps after the post-epilogue1 __syncthreads below.
    copy_w_to_smem(sm + B_OFF(1, 0), g_wh[1][l], tid);
    copy_w_to_smem(sm + B_OFF(1, 1), g_wl[1][l], tid);
    __syncthreads();

    // epilogue1 (registers): t = relu(D1 + b1) -> split back into Ah/Al
#pragma unroll
    for (int i = 0; i < 2; ++i)
#pragma unroll
        for (int j = 0; j < 8; ++j) {
            int gc = wc * 64 + j * 8 + et;
            float ba = bias[gc], bb = bias[gc + 1];
#pragma unroll
            for (int h = 0; h < 2; ++h) {
                int row = wr * 32 + i * 16 + eg + h * 8;
                float t0 = fmaxf(cf[i][j][2 * h] + ba, 0.f);
                float t1 = fmaxf(cf[i][j][2 * h + 1] + bb, 0.f);
                __nv_bfloat16 h0 = __float2bfloat16(t0), h1 = __float2bfloat16(t1);
                __nv_bfloat162 ph(h0, h1);
                __nv_bfloat162 pl(__float2bfloat16(t0 - __bfloat162float(h0)),
                                  __float2bfloat16(t1 - __bfloat162float(h1)));
                size_t boff = (size_t)row * (LDA * 2) + gc * 2;
                *reinterpret_cast<uint32_t*>(sm + A_HI_OFF + boff) =
                    *reinterpret_cast<uint32_t*>(&ph);
                *reinterpret_cast<uint32_t*>(sm + A_LO_OFF + boff) =
                    *reinterpret_cast<uint32_t*>(&pl);
            }
        }
    __syncthreads();

    // ================= GEMM2 =================
#pragma unroll
    for (int i = 0; i < 2; ++i)
#pragma unroll
        for (int j = 0; j < 8; ++j)
#pragma unroll
            for (int q = 0; q < 4; ++q) cf[i][j][q] = 0.f;
    {
        const uint32_t Ab[3] = {ah_b, ah_b, al_b};
        const uint32_t Bb[3] = {b2h, b2l, b2h};
#pragma unroll
        for (int p = 0; p < 3; ++p)
#pragma unroll
            for (int k = 0; k < 8; ++k) {
                uint32_t a[2][4];
#pragma unroll
                for (int i = 0; i < 2; ++i)
                    ldsm_x4(a[i], Ab[p] +
                        ((wr * 32 + i * 16 + a_row) * LDA + k * 16 + a_koff) * 2);
                uint32_t b[8][2];
#pragma unroll
                for (int q = 0; q < 4; ++q) {
                    uint32_t r4[4];
                    ldsm_x4t(r4, Bb[p] +
                        ((k * 16 + b_krow) * LDA + wc * 64 + q * 16 + b_noff) * 2);
                    b[2 * q][0] = r4[0]; b[2 * q][1] = r4[1];
                    b[2 * q + 1][0] = r4[2]; b[2 * q + 1][1] = r4[3];
                }
#pragma unroll
                for (int i = 0; i < 2; ++i)
#pragma unroll
                    for (int j = 0; j < 8; ++j)
                        mma16816(cf[i][j], a[i], b[j]);
            }
    }
    // epilogue2 (registers): h = relu(D2 + b2) -> global float2 stores
    float* hout = g_h[outsel];
#pragma unroll
    for (int i = 0; i < 2; ++i)
#pragma unroll
        for (int j = 0; j < 8; ++j) {
            int gc = wc * 64 + j * 8 + et;
            float ba = bias[128 + gc], bb = bias[128 + gc + 1];
#pragma unroll
            for (int h = 0; h < 2; ++h) {
                int grow = row0 + wr * 32 + i * 16 + eg + h * 8;
                if (grow < NN) {
                    float2 o;
                    o.x = fmaxf(cf[i][j][2 * h] + ba, 0.f);
                    o.y = fmaxf(cf[i][j][2 * h + 1] + bb, 0.f);
                    *reinterpret_cast<float2*>(hout + (size_t)grow * DD + gc) = o;
                }
            }
        }
}

// ---------------------------------------------------------------------------
// Fused pool + head: block per graph (contiguous node range), no atomics.
// ---------------------------------------------------------------------------
__global__ __launch_bounds__(128) void pool_head_kernel(
    const float* __restrict__ Wh, const float* __restrict__ bh,
    float* __restrict__ out) {
    const float* cur = g_h[(LL - 1) & 1];
    const int g = blockIdx.x;
    const int d = threadIdx.x;   // 128 threads: one per feature dim
    const int s = g_gstart[g];
    const int e = g_gend[g];
    float sum = 0.f;
    int r = s;
    for (; r + 2 <= e; r += 2) {
        sum += cur[(size_t)r * DD + d];
        sum += cur[(size_t)(r + 1) * DD + d];
    }
    if (r < e) sum += cur[(size_t)r * DD + d];
    float cnt = (float)(e - s);
    float v = sum / fmaxf(cnt, 1.f) * Wh[d];
#pragma unroll
    for (int o = 16; o > 0; o >>= 1)
        v += __shfl_down_sync(0xffffffffu, v, o);
    __shared__ float red[4];
    if ((d & 31) == 0) red[d >> 5] = v;
    __syncthreads();
    if (d == 0) out[g] = red[0] + red[1] + red[2] + red[3] + bh[0];
}

// Cleanup for graph replays (g_deg/g_cursor must be zero on next entry).
__global__ void cleanup_kernel() {
    int i = blockIdx.x * blockDim.x + threadIdx.x;
    if (i < NN) { g_deg[i] = 0; g_cursor[i] = 0; }
}

// ---------------------------------------------------------------------------
extern "C" void kernel_launch(void* const* d_in, const int* in_sizes, int n_in,
                              void* d_out, int out_size) {
    const float* x    = (const float*)d_in[0];
    const int*   ei   = (const int*)  d_in[1];
    const int*   batch= (const int*)  d_in[2];
    const float* W1s  = (const float*)d_in[3];
    const float* b1s  = (const float*)d_in[4];
    const float* W2s  = (const float*)d_in[5];
    const float* b2s  = (const float*)d_in[6];
    const float* Wh   = (const float*)d_in[7];
    const float* bh   = (const float*)d_in[8];
    float* out = (float*)d_out;

    static bool attr_done = false;
    if (!attr_done) {
        cudaFuncSetAttribute(mlp_mma_kernel,
                             cudaFuncAttributeMaxDynamicSharedMemorySize,
                             MLP_SMEM);
        attr_done = true;
    }

    prep_w_kernel<<<640, 256>>>(W1s, W2s);

    deg_count_kernel<<<EE / 256, 256>>>(ei);
    scan_blocks_kernel<<<NB, SCAN_B>>>();
    fill_off_kernel<<<(NN + 255) / 256, 256>>>();
    fill_adj_kernel<<<EE / 256, 256>>>(ei);
    boundary_kernel<<<(NN + 255) / 256, 256>>>(batch);

    int insel = -1;
    for (int l = 0; l < LL; ++l) {
        gather_kernel<<<NN * 32 / 256, 256>>>(x, insel);
        mlp_mma_kernel<<<(NN + 127) / 128, 256, MLP_SMEM>>>(l, l & 1, b1s, b2s);
        insel = l & 1;
    }
    pool_head_kernel<<<GG, 128>>>(Wh, bh, out);
    cleanup_kernel<<<(NN + 255) / 256, 256>>>();
}

// round 17
// speedup vs baseline: 1.4937x; 1.4937x over previous
#include <cuda_runtime.h>
#include <cuda_bf16.h>
#include <cstdint>

#define NN 50000
#define EE 800000
#define DD 128
#define LL 5
#define GG 1000

#define SCAN_B 512
#define NB ((NN + SCAN_B - 1) / SCAN_B)   // 98

// ---------------------------------------------------------------------------
// Device global scratch (no allocation allowed)
// ---------------------------------------------------------------------------
__device__ float g_z[NN * DD];
__device__ float g_h[2][NN * DD];
__device__ int g_deg[NN];      // zero on entry; pool_head_kernel restores
__device__ int g_off[NN];
__device__ int g_cursor[NN];   // zero on entry; pool_head_kernel restores
__device__ int g_adj[EE];
__device__ int g_scan[NB * SCAN_B];
__device__ int g_bsums[NB];
__device__ int g_gstart[GG];
__device__ int g_gend[GG];
// Pre-split weight images [mat(0=W1,1=W2)][layer][k*128+n]
__device__ __nv_bfloat16 g_wh[2][LL][DD * DD];
__device__ __nv_bfloat16 g_wl[2][LL][DD * DD];

// ---------------------------------------------------------------------------
// CSR build
// ---------------------------------------------------------------------------
__global__ void deg_count_kernel(const int* __restrict__ ei) {
    int e = blockIdx.x * blockDim.x + threadIdx.x;   // exact grid EE/256
    atomicAdd(&g_deg[ei[EE + e]], 1);
}
__global__ void scan_blocks_kernel() {
    __shared__ int s[SCAN_B];
    int tid = threadIdx.x;
    int i = blockIdx.x * SCAN_B + tid;
    int v = (i < NN) ? g_deg[i] : 0;
    s[tid] = v;
    __syncthreads();
#pragma unroll
    for (int o = 1; o < SCAN_B; o <<= 1) {
        int t = 0;
        if (tid >= o) t = s[tid - o];
        __syncthreads();
        s[tid] += t;
        __syncthreads();
    }
    g_scan[i] = s[tid];
    if (tid == SCAN_B - 1) g_bsums[blockIdx.x] = s[tid];
}
// fill_off with the top-level scan fused in (each block reduces bsums itself)
__global__ void fill_off_kernel() {
    __shared__ int warp_s[8];
    __shared__ int boff_s;
    const int tid = threadIdx.x;
    const int sb = blockIdx.x >> 1;            // scan-bucket of this block
    int v = (tid < NB && tid < sb) ? g_bsums[tid] : 0;
#pragma unroll
    for (int o = 16; o > 0; o >>= 1)
        v += __shfl_down_sync(0xffffffffu, v, o);
    if ((tid & 31) == 0) warp_s[tid >> 5] = v;
    __syncthreads();
    if (tid == 0) {
        int s = 0;
#pragma unroll
        for (int w = 0; w < 8; ++w) s += warp_s[w];
        boff_s = s;
    }
    __syncthreads();
    int i = blockIdx.x * 256 + tid;
    if (i < NN) g_off[i] = g_scan[i] - g_deg[i] + boff_s;
}
__global__ void fill_adj_kernel(const int* __restrict__ ei) {
    int e = blockIdx.x * blockDim.x + threadIdx.x;
    int dst = ei[EE + e];
    int pos = atomicAdd(&g_cursor[dst], 1);
    g_adj[g_off[dst] + pos] = ei[e];
}

// Graph boundary detection (batch is sorted).
__global__ void boundary_kernel(const int* __restrict__ batch) {
    int i = blockIdx.x * blockDim.x + threadIdx.x;
    if (i < NN) {
        int b = batch[i];
        if (i == 0 || batch[i - 1] != b) g_gstart[b] = i;
        if (i == NN - 1 || batch[i + 1] != b) g_gend[b] = i + 1;
    }
}

// ---------------------------------------------------------------------------
// Weight pre-split + boundary-array init (fused)
// ---------------------------------------------------------------------------
__global__ void prep_w_kernel(const float* __restrict__ W1s,
                              const float* __restrict__ W2s) {
    int idx = blockIdx.x * 256 + threadIdx.x;   // 640*256 = 163840 exact
    int l = idx / 32768;
    int rem = idx & 32767;
    int mat = rem >> 14;
    int e = rem & 16383;
    const float* W = mat ? W2s : W1s;
    float w = W[(size_t)l * 16384 + e];
    __nv_bfloat16 hi = __float2bfloat16(w);
    float lo = w - __bfloat162float(hi);
    g_wh[mat][l][e] = hi;
    g_wl[mat][l][e] = __float2bfloat16(lo);
    if (idx < GG) { g_gstart[idx] = 0; g_gend[idx] = 0; }
}

// ---------------------------------------------------------------------------
// Gather: z = h + sum_{j in adj(node)} h[j]   (high occupancy, LTS roofline)
// ---------------------------------------------------------------------------
__global__ __launch_bounds__(256) void gather_kernel(const float* __restrict__ x,
                                                     int insel) {
    const float* cur = (insel < 0) ? x : g_h[insel];
    int t = blockIdx.x * 256 + threadIdx.x;
    int node = t >> 5;
    int lane = t & 31;
    int off = 0, deg = 0;
    if (lane == 0) { off = g_off[node]; deg = g_deg[node]; }
    off = __shfl_sync(0xffffffffu, off, 0);
    deg = __shfl_sync(0xffffffffu, deg, 0);
    float4 acc = reinterpret_cast<const float4*>(cur + (size_t)node * DD)[lane];
    for (int j0 = 0; j0 < deg; j0 += 32) {
        int myidx = 0;
        if (j0 + lane < deg) myidx = g_adj[off + j0 + lane];
        int cnt = min(32, deg - j0);
        int tt = 0;
        for (; tt + 4 <= cnt; tt += 4) {
            int s0 = __shfl_sync(0xffffffffu, myidx, tt);
            int s1 = __shfl_sync(0xffffffffu, myidx, tt + 1);
            int s2 = __shfl_sync(0xffffffffu, myidx, tt + 2);
            int s3 = __shfl_sync(0xffffffffu, myidx, tt + 3);
            float4 v0 = reinterpret_cast<const float4*>(cur + (size_t)s0 * DD)[lane];
            float4 v1 = reinterpret_cast<const float4*>(cur + (size_t)s1 * DD)[lane];
            float4 v2 = reinterpret_cast<const float4*>(cur + (size_t)s2 * DD)[lane];
            float4 v3 = reinterpret_cast<const float4*>(cur + (size_t)s3 * DD)[lane];
            acc.x += v0.x; acc.y += v0.y; acc.z += v0.z; acc.w += v0.w;
            acc.x += v1.x; acc.y += v1.y; acc.z += v1.z; acc.w += v1.w;
            acc.x += v2.x; acc.y += v2.y; acc.z += v2.z; acc.w += v2.w;
            acc.x += v3.x; acc.y += v3.y; acc.z += v3.z; acc.w += v3.w;
        }
        for (; tt < cnt; ++tt) {
            int s0 = __shfl_sync(0xffffffffu, myidx, tt);
            float4 v0 = reinterpret_cast<const float4*>(cur + (size_t)s0 * DD)[lane];
            acc.x += v0.x; acc.y += v0.y; acc.z += v0.z; acc.w += v0.w;
        }
    }
    reinterpret_cast<float4*>(g_z + (size_t)node * DD)[lane] = acc;
}

// ---------------------------------------------------------------------------
// Raw mma.sync bf16 3-split fused 2-layer MLP (non-persistent, 391 CTAs).
// 128 rows/CTA, 256 threads = 8 warps tiled 4(row) x 2(col).
// ALL weight copies in the prologue (before accumulators are live — R15's
// deferred copy caused accumulator spills).
// ---------------------------------------------------------------------------
#define LDA 136
#define A_HI_OFF 0
#define A_LO_OFF 34816
#define B_OFF(m, p) (69632 + (m) * 69632 + (p) * 34816)
#define BIAS_OFF 208896
#define MLP_SMEM (BIAS_OFF + 256 * 4)   // 209920 bytes

__device__ __forceinline__ uint32_t smem_u32(const void* p) {
    uint32_t a;
    asm("{ .reg .u64 t; cvta.to.shared.u64 t, %1; cvt.u32.u64 %0, t; }"
        : "=r"(a) : "l"(p));
    return a;
}
__device__ __forceinline__ void ldsm_x4(uint32_t* r, uint32_t addr) {
    asm volatile("ldmatrix.sync.aligned.m8n8.x4.shared.b16 {%0,%1,%2,%3}, [%4];"
                 : "=r"(r[0]), "=r"(r[1]), "=r"(r[2]), "=r"(r[3]) : "r"(addr));
}
__device__ __forceinline__ void ldsm_x4t(uint32_t* r, uint32_t addr) {
    asm volatile("ldmatrix.sync.aligned.m8n8.x4.trans.shared.b16 {%0,%1,%2,%3}, [%4];"
                 : "=r"(r[0]), "=r"(r[1]), "=r"(r[2]), "=r"(r[3]) : "r"(addr));
}
__device__ __forceinline__ void mma16816(float* c, const uint32_t* a,
                                         const uint32_t* b) {
    asm volatile("mma.sync.aligned.m16n8k16.row.col.f32.bf16.bf16.f32 "
                 "{%0,%1,%2,%3}, {%4,%5,%6,%7}, {%8,%9}, {%0,%1,%2,%3};"
                 : "+f"(c[0]), "+f"(c[1]), "+f"(c[2]), "+f"(c[3])
                 : "r"(a[0]), "r"(a[1]), "r"(a[2]), "r"(a[3]),
                   "r"(b[0]), "r"(b[1]));
}
__device__ __forceinline__ void copy_w_to_smem(char* dst,
                                               const __nv_bfloat16* src,
                                               int tid) {
#pragma unroll
    for (int it = 0; it < 8; ++it) {
        int idx = it * 256 + tid;       // 2048 uint4 total
        int k = idx >> 4;
        int q = idx & 15;
        *reinterpret_cast<uint4*>(dst + (size_t)k * (LDA * 2) + q * 16) =
            reinterpret_cast<const uint4*>(src + (size_t)k * DD)[q];
    }
}

__global__ __launch_bounds__(256) void mlp_mma_kernel(
    int l, int outsel,
    const float* __restrict__ b1s, const float* __restrict__ b2s) {
    extern __shared__ char sm[];
    float* bias = reinterpret_cast<float*>(sm + BIAS_OFF);

    const int tid = threadIdx.x;
    const int wid = tid >> 5;
    const int lane = tid & 31;
    const int wr = wid >> 1;          // 0..3 row tile
    const int wc = wid & 1;           // 0..1 col tile
    const int row0 = blockIdx.x * 128;

    const uint32_t ah_b = smem_u32(sm + A_HI_OFF);
    const uint32_t al_b = smem_u32(sm + A_LO_OFF);
    const uint32_t b1h = smem_u32(sm + B_OFF(0, 0));
    const uint32_t b1l = smem_u32(sm + B_OFF(0, 1));
    const uint32_t b2h = smem_u32(sm + B_OFF(1, 0));
    const uint32_t b2l = smem_u32(sm + B_OFF(1, 1));

    if (tid < 128) bias[tid] = b1s[(size_t)l * DD + tid];
    else bias[tid] = b2s[(size_t)l * DD + (tid - 128)];

    copy_w_to_smem(sm + B_OFF(0, 0), g_wh[0][l], tid);
    copy_w_to_smem(sm + B_OFF(0, 1), g_wl[0][l], tid);
    copy_w_to_smem(sm + B_OFF(1, 0), g_wh[1][l], tid);
    copy_w_to_smem(sm + B_OFF(1, 1), g_wl[1][l], tid);

    // z rows -> split into Ah/Al
#pragma unroll
    for (int it = 0; it < 16; ++it) {
        int i = it * 256 + tid;
        int r = i >> 5, c4 = i & 31;
        int grow = row0 + r;
        float4 v = make_float4(0.f, 0.f, 0.f, 0.f);
        if (grow < NN)
            v = *reinterpret_cast<const float4*>(g_z + (size_t)grow * DD + c4 * 4);
        __nv_bfloat16 hx = __float2bfloat16(v.x), hy = __float2bfloat16(v.y);
        __nv_bfloat16 hz = __float2bfloat16(v.z), hw = __float2bfloat16(v.w);
        __nv_bfloat162 ph0(hx, hy), ph1(hz, hw);
        __nv_bfloat162 pl0(__float2bfloat16(v.x - __bfloat162float(hx)),
                           __float2bfloat16(v.y - __bfloat162float(hy)));
        __nv_bfloat162 pl1(__float2bfloat16(v.z - __bfloat162float(hz)),
                           __float2bfloat16(v.w - __bfloat162float(hw)));
        uint2 hi, lo;
        hi.x = *reinterpret_cast<uint32_t*>(&ph0);
        hi.y = *reinterpret_cast<uint32_t*>(&ph1);
        lo.x = *reinterpret_cast<uint32_t*>(&pl0);
        lo.y = *reinterpret_cast<uint32_t*>(&pl1);
        size_t boff = (size_t)r * (LDA * 2) + c4 * 8;
        *reinterpret_cast<uint2*>(sm + A_HI_OFF + boff) = hi;
        *reinterpret_cast<uint2*>(sm + A_LO_OFF + boff) = lo;
    }
    __syncthreads();

    const int a_row = lane & 15;
    const int a_koff = (lane >> 4) * 8;
    const int b_krow = (lane & 7) + ((lane >> 3) & 1) * 8;
    const int b_noff = (lane >> 4) * 8;
    const int eg = lane >> 2;
    const int et = 2 * (lane & 3);

    float cf[2][8][4];

    // ================= GEMM1 =================
#pragma unroll
    for (int i = 0; i < 2; ++i)
#pragma unroll
        for (int j = 0; j < 8; ++j)
#pragma unroll
            for (int q = 0; q < 4; ++q) cf[i][j][q] = 0.f;
    {
        const uint32_t Ab[3] = {ah_b, ah_b, al_b};
        const uint32_t Bb[3] = {b1h, b1l, b1h};
#pragma unroll
        for (int p = 0; p < 3; ++p)
#pragma unroll
            for (int k = 0; k < 8; ++k) {
                uint32_t a[2][4];
#pragma unroll
                for (int i = 0; i < 2; ++i)
                    ldsm_x4(a[i], Ab[p] +
                        ((wr * 32 + i * 16 + a_row) * LDA + k * 16 + a_koff) * 2);
                uint32_t b[8][2];
#pragma unroll
                for (int q = 0; q < 4; ++q) {
                    uint32_t r4[4];
                    ldsm_x4t(r4, Bb[p] +
                        ((k * 16 + b_krow) * LDA + wc * 64 + q * 16 + b_noff) * 2);
                    b[2 * q][0] = r4[0]; b[2 * q][1] = r4[1];
                    b[2 * q + 1][0] = r4[2]; b[2 * q + 1][1] = r4[3];
                }
#pragma unroll
                for (int i = 0; i < 2; ++i)
#pragma unroll
                    for (int j = 0; j < 8; ++j)
                        mma16816(cf[i][j], a[i], b[j]);
            }
    }
    __syncthreads();

    // epilogue1 (registers): t = relu(D1 + b1) -> split back into Ah/Al
#pragma unroll
    for (int i = 0; i < 2; ++i)
#pragma unroll
        for (int j = 0; j < 8; ++j) {
            int gc = wc * 64 + j * 8 + et;
            float ba = bias[gc], bb = bias[gc + 1];
#pragma unroll
            for (int h = 0; h < 2; ++h) {
                int row = wr * 32 + i * 16 + eg + h * 8;
                float t0 = fmaxf(cf[i][j][2 * h] + ba, 0.f);
                float t1 = fmaxf(cf[i][j][2 * h + 1] + bb, 0.f);
                __nv_bfloat16 h0 = __float2bfloat16(t0), h1 = __float2bfloat16(t1);
                __nv_bfloat162 ph(h0, h1);
                __nv_bfloat162 pl(__float2bfloat16(t0 - __bfloat162float(h0)),
                                  __float2bfloat16(t1 - __bfloat162float(h1)));
                size_t boff = (size_t)row * (LDA * 2) + gc * 2;
                *reinterpret_cast<uint32_t*>(sm + A_HI_OFF + boff) =
                    *reinterpret_cast<uint32_t*>(&ph);
                *reinterpret_cast<uint32_t*>(sm + A_LO_OFF + boff) =
                    *reinterpret_cast<uint32_t*>(&pl);
            }
        }
    __syncthreads();

    // ================= GEMM2 =================
#pragma unroll
    for (int i = 0; i < 2; ++i)
#pragma unroll
        for (int j = 0; j < 8; ++j)
#pragma unroll
            for (int q = 0; q < 4; ++q) cf[i][j][q] = 0.f;
    {
        const uint32_t Ab[3] = {ah_b, ah_b, al_b};
        const uint32_t Bb[3] = {b2h, b2l, b2h};
#pragma unroll
        for (int p = 0; p < 3; ++p)
#pragma unroll
            for (int k = 0; k < 8; ++k) {
                uint32_t a[2][4];
#pragma unroll
                for (int i = 0; i < 2; ++i)
                    ldsm_x4(a[i], Ab[p] +
                        ((wr * 32 + i * 16 + a_row) * LDA + k * 16 + a_koff) * 2);
                uint32_t b[8][2];
#pragma unroll
                for (int q = 0; q < 4; ++q) {
                    uint32_t r4[4];
                    ldsm_x4t(r4, Bb[p] +
                        ((k * 16 + b_krow) * LDA + wc * 64 + q * 16 + b_noff) * 2);
                    b[2 * q][0] = r4[0]; b[2 * q][1] = r4[1];
                    b[2 * q + 1][0] = r4[2]; b[2 * q + 1][1] = r4[3];
                }
#pragma unroll
                for (int i = 0; i < 2; ++i)
#pragma unroll
                    for (int j = 0; j < 8; ++j)
                        mma16816(cf[i][j], a[i], b[j]);
            }
    }
    // epilogue2 (registers): h = relu(D2 + b2) -> global float2 stores
    float* hout = g_h[outsel];
#pragma unroll
    for (int i = 0; i < 2; ++i)
#pragma unroll
        for (int j = 0; j < 8; ++j) {
            int gc = wc * 64 + j * 8 + et;
            float ba = bias[128 + gc], bb = bias[128 + gc + 1];
#pragma unroll
            for (int h = 0; h < 2; ++h) {
                int grow = row0 + wr * 32 + i * 16 + eg + h * 8;
                if (grow < NN) {
                    float2 o;
                    o.x = fmaxf(cf[i][j][2 * h] + ba, 0.f);
                    o.y = fmaxf(cf[i][j][2 * h + 1] + bb, 0.f);
                    *reinterpret_cast<float2*>(hout + (size_t)grow * DD + gc) = o;
                }
            }
        }
}

// ---------------------------------------------------------------------------
// Fused pool + head: block per graph (contiguous node range), no atomics.
// Also restores the g_deg/g_cursor zero-invariant for graph replays.
// ---------------------------------------------------------------------------
__global__ __launch_bounds__(128) void pool_head_kernel(
    const float* __restrict__ Wh, const float* __restrict__ bh,
    float* __restrict__ out) {
    // replay cleanup: 1000 blocks x 128 threads = 128000 >= NN
    int ci = blockIdx.x * 128 + threadIdx.x;
    if (ci < NN) { g_deg[ci] = 0; g_cursor[ci] = 0; }

    const float* cur = g_h[(LL - 1) & 1];
    const int g = blockIdx.x;
    const int d = threadIdx.x;   // 128 threads: one per feature dim
    const int s = g_gstart[g];
    const int e = g_gend[g];
    float sum = 0.f;
    int r = s;
    for (; r + 2 <= e; r += 2) {
        sum += cur[(size_t)r * DD + d];
        sum += cur[(size_t)(r + 1) * DD + d];
    }
    if (r < e) sum += cur[(size_t)r * DD + d];
    float cnt = (float)(e - s);
    float v = sum / fmaxf(cnt, 1.f) * Wh[d];
#pragma unroll
    for (int o = 16; o > 0; o >>= 1)
        v += __shfl_down_sync(0xffffffffu, v, o);
    __shared__ float red[4];
    if ((d & 31) == 0) red[d >> 5] = v;
    __syncthreads();
    if (d == 0) out[g] = red[0] + red[1] + red[2] + red[3] + bh[0];
}

// ---------------------------------------------------------------------------
extern "C" void kernel_launch(void* const* d_in, const int* in_sizes, int n_in,
                              void* d_out, int out_size) {
    const float* x    = (const float*)d_in[0];
    const int*   ei   = (const int*)  d_in[1];
    const int*   batch= (const int*)  d_in[2];
    const float* W1s  = (const float*)d_in[3];
    const float* b1s  = (const float*)d_in[4];
    const float* W2s  = (const float*)d_in[5];
    const float* b2s  = (const float*)d_in[6];
    const float* Wh   = (const float*)d_in[7];
    const float* bh   = (const float*)d_in[8];
    float* out = (float*)d_out;

    static bool attr_done = false;
    if (!attr_done) {
        cudaFuncSetAttribute(mlp_mma_kernel,
                             cudaFuncAttributeMaxDynamicSharedMemorySize,
                             MLP_SMEM);
        attr_done = true;
    }

    prep_w_kernel<<<640, 256>>>(W1s, W2s);

    deg_count_kernel<<<EE / 256, 256>>>(ei);
    scan_blocks_kernel<<<NB, SCAN_B>>>();
    fill_off_kernel<<<(NN + 255) / 256, 256>>>();
    fill_adj_kernel<<<EE / 256, 256>>>(ei);
    boundary_kernel<<<(NN + 255) / 256, 256>>>(batch);

    int insel = -1;
    for (int l = 0; l < LL; ++l) {
        gather_kernel<<<NN * 32 / 256, 256>>>(x, insel);
        mlp_mma_kernel<<<(NN + 127) / 128, 256, MLP_SMEM>>>(l, l & 1, b1s, b2s);
        insel = l & 1;
    }
    pool_head_kernel<<<GG, 128>>>(Wh, bh, out);
}